// round 3
// baseline (speedup 1.0000x reference)
#include <cuda_runtime.h>
#include <math.h>

// Problem constants (fixed by dataset): B=64, Lq=Lk=1024, D=64
#define BDIM   64
#define LDIM   1024
#define DDIM   64
#define TQ     16          // q rows per CTA
#define KT     256         // k columns per GEMM1 tile
#define NTHR   256
#define SROW   1028        // scores smem row stride (floats), +4 pad
#define KROW   68          // k/v tile smem row stride (floats), +4 pad

// smem layout (floats): q_s[16*68] | kv_s[256*68] | sc_s[16*1028]
#define SMEM_FLOATS (TQ*KROW + KT*KROW + TQ*SROW)

__global__ __launch_bounds__(NTHR, 1)
void sparse_attn_kernel(const float* __restrict__ qg_,
                        const float* __restrict__ kg_,
                        const float* __restrict__ vg_,
                        const int* __restrict__ maskg,      // bool -> int32 in harness
                        float* __restrict__ outg,
                        float* __restrict__ attng)
{
    extern __shared__ float smem[];
    float* q_s  = smem;                       // 16 x 68
    float* kv_s = q_s + TQ * KROW;            // 256 x 68
    float* sc_s = kv_s + KT * KROW;           // 16 x 1028

    const int qt  = blockIdx.x;               // 0..63 (q tile)
    const int b   = blockIdx.y;               // 0..63 (batch)
    const int tid = threadIdx.x;

    const int q_row0 = qt * TQ;
    const float* qg = qg_ + ((size_t)b * LDIM + q_row0) * DDIM;
    const float* kg = kg_ + (size_t)b * LDIM * DDIM;
    const float* vg = vg_ + (size_t)b * LDIM * DDIM;

    // ---- load q tile, pre-scaled by 1/TEMPERATURE ----
    {
        const int r  = tid >> 4;
        const int c4 = (tid & 15) * 4;
        float4 t = *(const float4*)(qg + r * DDIM + c4);
        const float inv = 0.125f; // 1/8
        float* dst = q_s + r * KROW + c4;
        dst[0] = t.x * inv; dst[1] = t.y * inv; dst[2] = t.z * inv; dst[3] = t.w * inv;
    }

    // ==================== GEMM1: scores = (q/8) . k^T ====================
    const int ty = tid >> 6;   // 0..3  -> rows ty*4 + r
    const int tx = tid & 63;   // 0..63 -> cols tx + 64*c
    for (int kt = 0; kt < LDIM / KT; kt++) {
        __syncthreads();   // also covers q_s load on first iter / kv_s reuse later
        // stage k tile [KT x 64] into kv_s
        #pragma unroll
        for (int i = 0; i < 16; i++) {
            int f   = i * NTHR + tid;
            int row = f >> 4;
            int c4  = (f & 15) * 4;
            *(float4*)(kv_s + row * KROW + c4) =
                *(const float4*)(kg + (size_t)(kt * KT + row) * DDIM + c4);
        }
        __syncthreads();

        float acc[4][4] = {};
        #pragma unroll
        for (int d = 0; d < DDIM; d += 4) {
            float4 qv[4], kv[4];
            #pragma unroll
            for (int r = 0; r < 4; r++) qv[r] = *(float4*)(q_s + (ty * 4 + r) * KROW + d);
            #pragma unroll
            for (int c = 0; c < 4; c++) kv[c] = *(float4*)(kv_s + (tx + 64 * c) * KROW + d);
            #pragma unroll
            for (int r = 0; r < 4; r++)
                #pragma unroll
                for (int c = 0; c < 4; c++)
                    acc[r][c] += qv[r].x * kv[c].x + qv[r].y * kv[c].y
                               + qv[r].z * kv[c].z + qv[r].w * kv[c].w;
        }
        #pragma unroll
        for (int r = 0; r < 4; r++)
            #pragma unroll
            for (int c = 0; c < 4; c++)
                sc_s[(ty * 4 + r) * SROW + kt * KT + tx + 64 * c] = acc[r][c];
    }
    __syncthreads();

    // ==================== mask + sparsemax (Michelot, exact) ====================
    const int row  = tid >> 4;   // 0..15
    const int sub  = tid & 15;   // 0..15 lanes per row
    const int grow = q_row0 + row;

    float z[64];
    {
        const int4* m4 = (const int4*)(maskg + ((size_t)b * LDIM + grow) * LDIM);
        #pragma unroll
        for (int jj = 0; jj < 16; jj++) {
            int col = sub * 4 + 64 * jj;
            int4  mb = m4[col >> 2];
            float4 s = *(float4*)(sc_s + row * SROW + col);
            z[jj * 4 + 0] = mb.x ? -INFINITY : s.x;
            z[jj * 4 + 1] = mb.y ? -INFINITY : s.y;
            z[jj * 4 + 2] = mb.z ? -INFINITY : s.z;
            z[jj * 4 + 3] = mb.w ? -INFINITY : s.w;
        }
    }

    float tau;
    {
        // pass 0: active = all unmasked
        float s = 0.0f; int c = 0;
        #pragma unroll
        for (int i = 0; i < 64; i++)
            if (z[i] > -INFINITY) { s += z[i]; c++; }
        #pragma unroll
        for (int o = 8; o >= 1; o >>= 1) {
            s += __shfl_xor_sync(0xffffffffu, s, o, 16);
            c += __shfl_xor_sync(0xffffffffu, c, o, 16);
        }
        tau = (c > 0) ? (s - 1.0f) / (float)c : INFINITY;
        int prev = c;
        for (int it = 0; it < 64; it++) {
            float s2 = 0.0f; int c2 = 0;
            #pragma unroll
            for (int i = 0; i < 64; i++)
                if (z[i] > tau) { s2 += z[i]; c2++; }
            #pragma unroll
            for (int o = 8; o >= 1; o >>= 1) {
                s2 += __shfl_xor_sync(0xffffffffu, s2, o, 16);
                c2 += __shfl_xor_sync(0xffffffffu, c2, o, 16);
            }
            bool done = (c2 == prev) || (c2 == 0);
            prev = c2;
            if (c2 > 0) tau = (s2 - 1.0f) / (float)c2;
            if (__all_sync(0xffffffffu, done)) break;
        }
    }

    // attn = max(z - tau, 0); write to smem (for GEMM2) and global
    {
        float* attn_row = attng + ((size_t)b * LDIM + grow) * LDIM;
        #pragma unroll
        for (int jj = 0; jj < 16; jj++) {
            int col = sub * 4 + 64 * jj;
            float4 a;
            a.x = fmaxf(z[jj * 4 + 0] - tau, 0.0f);
            a.y = fmaxf(z[jj * 4 + 1] - tau, 0.0f);
            a.z = fmaxf(z[jj * 4 + 2] - tau, 0.0f);
            a.w = fmaxf(z[jj * 4 + 3] - tau, 0.0f);
            *(float4*)(sc_s + row * SROW + col) = a;
            *(float4*)(attn_row + col) = a;
        }
    }

    // ==================== GEMM2: out = attn . v ====================
    const int w    = tid >> 5;         // warp 0..7 -> k-slice
    const int lane = tid & 31;
    const int rp   = lane & 7;         // rows rp, rp+8
    const int cg   = lane >> 3;        // col group: cols cg*16 .. +15
    float4 acc0[4] = {}, acc1[4] = {};

    for (int ch = 0; ch < 4; ch++) {
        __syncthreads();   // protects sc_s (first iter) and kv_s reuse
        // stage v chunk [256 x 64]
        #pragma unroll
        for (int i = 0; i < 16; i++) {
            int f   = i * NTHR + tid;
            int r   = f >> 4;
            int c4  = (f & 15) * 4;
            *(float4*)(kv_s + r * KROW + c4) =
                *(const float4*)(vg + (size_t)(ch * 256 + r) * DDIM + c4);
        }
        __syncthreads();

        const int jbase = w * 32;
        #pragma unroll 8
        for (int j = 0; j < 32; j++) {
            int vr = jbase + j;                       // row within chunk
            float a0 = sc_s[rp * SROW + ch * 256 + vr];
            float a1 = sc_s[(rp + 8) * SROW + ch * 256 + vr];
            #pragma unroll
            for (int g = 0; g < 4; g++) {
                float4 vv = *(float4*)(kv_s + vr * KROW + cg * 16 + g * 4);
                acc0[g].x += a0 * vv.x; acc0[g].y += a0 * vv.y;
                acc0[g].z += a0 * vv.z; acc0[g].w += a0 * vv.w;
                acc1[g].x += a1 * vv.x; acc1[g].y += a1 * vv.y;
                acc1[g].z += a1 * vv.z; acc1[g].w += a1 * vv.w;
            }
        }
    }
    __syncthreads();

    // cross-warp reduction of the 16x64 partials through sc_s
    float* red = sc_s;   // 8 * 1024 floats, fits
    #pragma unroll
    for (int g = 0; g < 4; g++) {
        *(float4*)(red + w * 1024 + rp * 64 + cg * 16 + g * 4)       = acc0[g];
        *(float4*)(red + w * 1024 + (rp + 8) * 64 + cg * 16 + g * 4) = acc1[g];
    }
    __syncthreads();
    {
        int o = tid * 4;            // 0..1020
        float4 sum = make_float4(0.f, 0.f, 0.f, 0.f);
        #pragma unroll
        for (int w2 = 0; w2 < 8; w2++) {
            float4 p = *(float4*)(red + w2 * 1024 + o);
            sum.x += p.x; sum.y += p.y; sum.z += p.z; sum.w += p.w;
        }
        int r = o >> 6, c = o & 63;
        *(float4*)(outg + ((size_t)b * LDIM + q_row0 + r) * DDIM + c) = sum;
    }
}

extern "C" void kernel_launch(void* const* d_in, const int* in_sizes, int n_in,
                              void* d_out, int out_size)
{
    const float* q    = (const float*)d_in[0];
    const float* k    = (const float*)d_in[1];
    const float* v    = (const float*)d_in[2];
    const int*   mask = (const int*)d_in[3];   // bool in reference -> int32 in harness

    float* out  = (float*)d_out;                                // [B, Lq, D]
    float* attn = (float*)d_out + (size_t)BDIM * LDIM * DDIM;   // [B, Lq, Lk]

    const size_t smem_bytes = SMEM_FLOATS * sizeof(float);      // ~140 KB
    cudaFuncSetAttribute(sparse_attn_kernel,
                         cudaFuncAttributeMaxDynamicSharedMemorySize,
                         (int)smem_bytes);

    dim3 grid(LDIM / TQ, BDIM);   // (64, 64)
    dim3 block(NTHR);
    sparse_attn_kernel<<<grid, block, smem_bytes>>>(q, k, v, mask, out, attn);
}